// round 12
// baseline (speedup 1.0000x reference)
#include <cuda_runtime.h>
#include <cuda_fp16.h>
#include <cstdint>

// ============================================================================
// Problem constants
// ============================================================================
#define NQ     6
#define DIM    64
#define NL     8
#define TILE   128           // batch rows per tile (8 warps x 16 rows)
#define GRIDB  296           // persistent CTAs (148 SMs x 2)

// ============================================================================
// PTX helpers (plain sm_103-legal)
// ============================================================================
__device__ __forceinline__ uint32_t smem_u32(const void* p) {
    uint32_t a;
    asm("{ .reg .u64 t; cvta.to.shared.u64 t, %1; cvt.u32.u64 %0, t; }" : "=r"(a) : "l"(p));
    return a;
}
__device__ __forceinline__ void ldsm_x4(uint32_t* r, uint32_t addr) {
    asm volatile("ldmatrix.sync.aligned.m8n8.x4.shared.b16 {%0,%1,%2,%3}, [%4];"
                 : "=r"(r[0]), "=r"(r[1]), "=r"(r[2]), "=r"(r[3]) : "r"(addr));
}
__device__ __forceinline__ void mma16816(float* c, const uint32_t* a, const uint32_t* b) {
    asm volatile("mma.sync.aligned.m16n8k16.row.col.f32.f16.f16.f32 "
                 "{%0,%1,%2,%3}, {%4,%5,%6,%7}, {%8,%9}, {%0,%1,%2,%3};"
                 : "+f"(c[0]), "+f"(c[1]), "+f"(c[2]), "+f"(c[3])
                 : "r"(a[0]), "r"(a[1]), "r"(a[2]), "r"(a[3]), "r"(b[0]), "r"(b[1]));
}

// ============================================================================
// Single fused persistent kernel.
//
// Per-CTA one-time build:
//   1. 48 threads: gate matrices (8 floats each) -> smem  (trig hoisted)
//   2. threads 0-63: Mt[d] = fc_w . Zsign  -> smem
//   3. each warp simulates 8 basis columns of U (lane = 2 amplitudes,
//      shfl-based gates), writes fp16 W directly into the k-permuted smem B.
//
// Tile loop (zero synchronization): 8 independent warps, each M=16 x N=128.
// A: one LDG.128 per row per k16-chunk straight into mma fragments via a
//    k-permutation (slots {2q,2q+1,2q+8,2q+9} <-> cols {4q..4q+3}); B smem is
//    staged in the matching permuted k-layout.  Cross-tile register prefetch.
// ============================================================================
#define STRIDE_B 144                          // 128B data + 16B pad, conflict-free
#define OF_MT    0                            // 64 float4 = 1 KB
#define OF_GATE  1024                         // 48 gates x 8 floats = 1536 B
#define OF_B     2560
#define SMEM_BYTES (OF_B + 128 * STRIDE_B)    // 2560 + 18432 = 20992

__global__ void __launch_bounds__(256, 2)
qnn_main(const float4* __restrict__ X, float4* __restrict__ out, int ntiles,
         const float* __restrict__ weights,
         const float* __restrict__ fc_w,
         const float* __restrict__ fc_b) {
    extern __shared__ char smc[];
    const uint32_t sm = smem_u32(smc);
    const int tid = threadIdx.x, wid = tid >> 5, lane = tid & 31;

    float* sGate = reinterpret_cast<float*>(smc + OF_GATE);
    float4* sMtw = reinterpret_cast<float4*>(smc + OF_MT);

    // ---- build step 1: gate matrices (one thread per gate) ----
    if (tid < NL * NQ) {
        const float* g = weights + tid * 3;
        float phi = g[0], th = g[1], om = g[2];
        float st, ct; sincosf(0.5f * th, &st, &ct);
        float sa, ca; sincosf(0.5f * (phi + om), &sa, &ca);
        float sb, cb; sincosf(0.5f * (phi - om), &sb, &cb);
        float* o = sGate + tid * 8;
        o[0] =  ca * ct;  o[1] = -sa * ct;    // m00
        o[2] = -cb * st;  o[3] = -sb * st;    // m01
        o[4] =  cb * st;  o[5] = -sb * st;    // m10
        o[6] =  ca * ct;  o[7] =  sa * ct;    // m11
    }
    // ---- build step 2: Mt (one thread per basis state) ----
    if (tid < DIM) {
        float m[4];
        for (int c = 0; c < 4; c++) {
            float acc = 0.f;
            for (int i = 0; i < NQ; i++) {
                int bit = (tid >> (5 - i)) & 1;
                acc += fc_w[c * NQ + i] * (bit ? -1.f : 1.f);
            }
            m[c] = acc;
        }
        sMtw[tid] = make_float4(m[0], m[1], m[2], m[3]);
    }
    const float4 fcb = make_float4(fc_b[0], fc_b[1], fc_b[2], fc_b[3]);
    __syncthreads();

    // ---- build step 3: each warp simulates 8 columns, writes permuted B ----
    for (int i = 0; i < 8; i++) {
        const int w = wid * 8 + i;          // basis column
        float sr0 = (lane == w) ? 1.f : 0.f,      si0 = 0.f;
        float sr1 = (lane + 32 == w) ? 1.f : 0.f, si1 = 0.f;

        for (int l = 0; l < NL; l++) {
            for (int q = 0; q < NQ; q++) {
                const float* gm = sGate + (l * NQ + q) * 8;
                float m00r = gm[0], m00i = gm[1], m01r = gm[2], m01i = gm[3];
                float m10r = gm[4], m10i = gm[5], m11r = gm[6], m11i = gm[7];
                int b = 5 - q;
                if (b == 5) {
                    float nr0 = m00r*sr0 - m00i*si0 + m01r*sr1 - m01i*si1;
                    float ni0 = m00r*si0 + m00i*sr0 + m01r*si1 + m01i*sr1;
                    float nr1 = m10r*sr0 - m10i*si0 + m11r*sr1 - m11i*si1;
                    float ni1 = m10r*si0 + m10i*sr0 + m11r*si1 + m11i*sr1;
                    sr0 = nr0; si0 = ni0; sr1 = nr1; si1 = ni1;
                } else {
                    int msk = 1 << b;
                    int bit = (lane >> b) & 1;
                    float dr = bit ? m11r : m00r, di = bit ? m11i : m00i;
                    float orr = bit ? m10r : m01r, oi = bit ? m10i : m01i;
                    float pr, pi, nr, ni;
                    pr = __shfl_xor_sync(0xffffffffu, sr0, msk);
                    pi = __shfl_xor_sync(0xffffffffu, si0, msk);
                    nr = dr*sr0 - di*si0 + orr*pr - oi*pi;
                    ni = dr*si0 + di*sr0 + orr*pi + oi*pr;
                    sr0 = nr; si0 = ni;
                    pr = __shfl_xor_sync(0xffffffffu, sr1, msk);
                    pi = __shfl_xor_sync(0xffffffffu, si1, msk);
                    nr = dr*sr1 - di*si1 + orr*pr - oi*pi;
                    ni = dr*si1 + di*sr1 + orr*pi + oi*pr;
                    sr1 = nr; si1 = ni;
                }
            }
            int r = (l % (NQ - 1)) + 1;
            for (int q = 0; q < NQ; q++) {
                int t = (q + r) % NQ;
                int bc = 5 - q, bt = 5 - t;
                if (bc == 5) {
                    int m = 1 << bt;
                    sr1 = __shfl_xor_sync(0xffffffffu, sr1, m);
                    si1 = __shfl_xor_sync(0xffffffffu, si1, m);
                } else if (bt == 5) {
                    if ((lane >> bc) & 1) {
                        float tmp;
                        tmp = sr0; sr0 = sr1; sr1 = tmp;
                        tmp = si0; si0 = si1; si1 = tmp;
                    }
                } else {
                    int m = 1 << bt;
                    int ctrl = (lane >> bc) & 1;
                    float pr, pi;
                    pr = __shfl_xor_sync(0xffffffffu, sr0, m);
                    pi = __shfl_xor_sync(0xffffffffu, si0, m);
                    if (ctrl) { sr0 = pr; si0 = pi; }
                    pr = __shfl_xor_sync(0xffffffffu, sr1, m);
                    pi = __shfl_xor_sync(0xffffffffu, si1, m);
                    if (ctrl) { sr1 = pr; si1 = pi; }
                }
            }
        }

        // permuted k-position for column w:
        // kpos = chunk | (b<<3) | (a<<1) | d  with a=(c>>2)&3, b=(c>>1)&1, d=c&1
        const int kpos = (w & 48) | (((w >> 1) & 1) << 3) | (((w >> 2) & 3) << 1) | (w & 1);
        char* bp = smc + OF_B + kpos * 2;
        *reinterpret_cast<__half*>(bp + (2 * lane)      * STRIDE_B) = __float2half(sr0);
        *reinterpret_cast<__half*>(bp + (2 * lane + 1)  * STRIDE_B) = __float2half(si0);
        *reinterpret_cast<__half*>(bp + (2 * lane + 64) * STRIDE_B) = __float2half(sr1);
        *reinterpret_cast<__half*>(bp + (2 * lane + 65) * STRIDE_B) = __float2half(si1);
    }
    __syncthreads();

    // ======================== main tile loop ========================
    const int m0 = wid * 16;              // rows m0 .. m0+15
    const int r0 = m0 + (lane >> 2);      // this thread's rows: r0, r0+8
    const int l4 = lane & 3;

    // ldsm x4 base: b[0]={n0-7,k0-7} b[1]={n0-7,k8-15} b[2]={n8-15,k0-7} b[3]={n8-15,k8-15}
    const uint32_t bB = sm + OF_B
        + (uint32_t)(((lane >> 4) & 1) * 8 + (lane & 7)) * STRIDE_B
        + ((lane >> 3) & 1) * 16;

    const float4* sMt = reinterpret_cast<const float4*>(smc + OF_MT);

    // per-thread gmem offsets (float4 units)
    const size_t o0 = (size_t)r0 * 16 + l4;        // + 4*kc ; row r0
    const size_t o1 = (size_t)(r0 + 8) * 16 + l4;  //         row r0+8

    // ---- prologue: prefetch first tile ----
    float4 pv[8];
    {
        const size_t tb = (size_t)blockIdx.x * TILE * 16;
        #pragma unroll
        for (int kc = 0; kc < 4; kc++) {
            pv[kc * 2]     = X[tb + o0 + 4 * kc];
            pv[kc * 2 + 1] = X[tb + o1 + 4 * kc];
        }
    }

    for (int t = blockIdx.x; t < ntiles; t += gridDim.x) {
        const int rowbase = t * TILE;

        // ---- issue next tile's loads early (overlap with compute below) ----
        float4 nv[8];
        {
            const int tn = (t + gridDim.x < ntiles) ? (t + gridDim.x) : t;
            const size_t tb = (size_t)tn * TILE * 16;
            #pragma unroll
            for (int kc = 0; kc < 4; kc++) {
                nv[kc * 2]     = X[tb + o0 + 4 * kc];
                nv[kc * 2 + 1] = X[tb + o1 + 4 * kc];
            }
        }

        float c[16][4];                  // [n8 group][quad]
        #pragma unroll
        for (int j = 0; j < 16; j++)
            #pragma unroll
            for (int q = 0; q < 4; q++) c[j][q] = 0.f;
        float ss0 = 0.f, ss1 = 0.f;      // sumsq rows r0, r0+8

        #pragma unroll
        for (int kc = 0; kc < 4; kc++) {
            // ---- A fragments from prefetched registers ----
            float4 v0 = pv[kc * 2];
            float4 v1 = pv[kc * 2 + 1];
            ss0 += v0.x * v0.x + v0.y * v0.y + v0.z * v0.z + v0.w * v0.w;
            ss1 += v1.x * v1.x + v1.y * v1.y + v1.z * v1.z + v1.w * v1.w;

            __half2 h00 = __floats2half2_rn(v0.x, v0.y);
            __half2 h01 = __floats2half2_rn(v0.z, v0.w);
            __half2 h10 = __floats2half2_rn(v1.x, v1.y);
            __half2 h11 = __floats2half2_rn(v1.z, v1.w);

            uint32_t ah[4];
            ah[0] = *reinterpret_cast<uint32_t*>(&h00);   // slots (2l4, 2l4+1)   row r0
            ah[1] = *reinterpret_cast<uint32_t*>(&h10);   //                      row r0+8
            ah[2] = *reinterpret_cast<uint32_t*>(&h01);   // slots (2l4+8, 2l4+9) row r0
            ah[3] = *reinterpret_cast<uint32_t*>(&h11);   //                      row r0+8

            // ---- full N=128: 8 n16 groups ----
            #pragma unroll
            for (int pr = 0; pr < 8; pr++) {
                uint32_t b[4];
                ldsm_x4(b, bB + (uint32_t)(pr * 16) * STRIDE_B + kc * 32);
                mma16816(c[pr * 2],     ah, b);
                mma16816(c[pr * 2 + 1], ah, b + 2);
            }
        }

        // ---- row norms (quad reduce) ----
        ss0 += __shfl_xor_sync(0xffffffffu, ss0, 1);
        ss0 += __shfl_xor_sync(0xffffffffu, ss0, 2);
        ss1 += __shfl_xor_sync(0xffffffffu, ss1, 1);
        ss1 += __shfl_xor_sync(0xffffffffu, ss1, 2);

        // ---- epilogue: p = re^2 + im^2 ; 4-class dot against Mt ----
        float a0[4] = {0.f, 0.f, 0.f, 0.f}, a1[4] = {0.f, 0.f, 0.f, 0.f};
        #pragma unroll
        for (int j = 0; j < 16; j++) {
            const int amp = j * 4 + l4;
            float4 mt = sMt[amp];
            float p0 = c[j][0] * c[j][0] + c[j][1] * c[j][1];
            float p1 = c[j][2] * c[j][2] + c[j][3] * c[j][3];
            a0[0] += mt.x * p0; a0[1] += mt.y * p0; a0[2] += mt.z * p0; a0[3] += mt.w * p0;
            a1[0] += mt.x * p1; a1[1] += mt.y * p1; a1[2] += mt.z * p1; a1[3] += mt.w * p1;
        }
        #pragma unroll
        for (int q = 0; q < 4; q++) {
            a0[q] += __shfl_xor_sync(0xffffffffu, a0[q], 1);
            a0[q] += __shfl_xor_sync(0xffffffffu, a0[q], 2);
            a1[q] += __shfl_xor_sync(0xffffffffu, a1[q], 1);
            a1[q] += __shfl_xor_sync(0xffffffffu, a1[q], 2);
        }

        if (l4 == 0) {
            float inv0 = 1.f / fmaxf(ss0, 1e-24f);
            float inv1 = 1.f / fmaxf(ss1, 1e-24f);
            float4 r;
            r.x = a0[0] * inv0 + fcb.x;
            r.y = a0[1] * inv0 + fcb.y;
            r.z = a0[2] * inv0 + fcb.z;
            r.w = a0[3] * inv0 + fcb.w;
            out[rowbase + r0] = r;
            r.x = a1[0] * inv1 + fcb.x;
            r.y = a1[1] * inv1 + fcb.y;
            r.z = a1[2] * inv1 + fcb.z;
            r.w = a1[3] * inv1 + fcb.w;
            out[rowbase + r0 + 8] = r;
        }

        // ---- rotate prefetch buffer ----
        #pragma unroll
        for (int i = 0; i < 8; i++) pv[i] = nv[i];
    }
}

// ============================================================================
// Launch — single kernel, single graph node
// ============================================================================
extern "C" void kernel_launch(void* const* d_in, const int* in_sizes, int n_in,
                              void* d_out, int out_size) {
    const float* x    = (const float*)d_in[0];
    const float* wts  = (const float*)d_in[1];
    const float* fc_w = (const float*)d_in[2];
    const float* fc_b = (const float*)d_in[3];

    int n_items = in_sizes[0] / DIM;   // 262144
    int ntiles  = n_items / TILE;      // 2048

    cudaFuncSetAttribute(qnn_main, cudaFuncAttributeMaxDynamicSharedMemorySize, SMEM_BYTES);
    qnn_main<<<GRIDB, 256, SMEM_BYTES>>>((const float4*)x, (float4*)d_out, ntiles,
                                         wts, fc_w, fc_b);
}

// round 13
// speedup vs baseline: 1.7457x; 1.7457x over previous
#include <cuda_runtime.h>
#include <cuda_fp16.h>
#include <cstdint>

// ============================================================================
// Problem constants
// ============================================================================
#define NQ     6
#define DIM    64
#define NL     8
#define TILE   128
#define GRIDB  296           // persistent CTAs (148 SMs x 2)

// Circuit constants built per-launch by qnn_build.
// W row 2a = Re(U[a][:]), row 2a+1 = Im(U[a][:]), fp16, 64 cols.
__device__ __align__(16) __half g_Wh[128 * 64];
__device__ __align__(16) float4 g_Mt[64];   // Mt[a] = {M[0][a],..,M[3][a]}, M = fc_w * Zsign^T
__device__ __align__(16) float4 g_fcb;
__device__ int g_ctr;                       // dynamic work counter (reset each launch)

// ============================================================================
// PTX helpers (plain sm_103-legal)
// ============================================================================
__device__ __forceinline__ uint32_t smem_u32(const void* p) {
    uint32_t a;
    asm("{ .reg .u64 t; cvta.to.shared.u64 t, %1; cvt.u32.u64 %0, t; }" : "=r"(a) : "l"(p));
    return a;
}
__device__ __forceinline__ void ldsm_x4(uint32_t* r, uint32_t addr) {
    asm volatile("ldmatrix.sync.aligned.m8n8.x4.shared.b16 {%0,%1,%2,%3}, [%4];"
                 : "=r"(r[0]), "=r"(r[1]), "=r"(r[2]), "=r"(r[3]) : "r"(addr));
}
__device__ __forceinline__ void mma16816(float* c, const uint32_t* a, const uint32_t* b) {
    asm volatile("mma.sync.aligned.m16n8k16.row.col.f32.f16.f16.f32 "
                 "{%0,%1,%2,%3}, {%4,%5,%6,%7}, {%8,%9}, {%0,%1,%2,%3};"
                 : "+f"(c[0]), "+f"(c[1]), "+f"(c[2]), "+f"(c[3])
                 : "r"(a[0]), "r"(a[1]), "r"(a[2]), "r"(a[3]), "r"(b[0]), "r"(b[1]));
}

// ============================================================================
// Kernel A: build U columns (one warp per basis column), emit Wh/Mt/fcb,
// reset the dynamic-work counter.
// ============================================================================
__global__ void qnn_build(const float* __restrict__ weights,
                          const float* __restrict__ fc_w,
                          const float* __restrict__ fc_b) {
    const int w = blockIdx.x;
    const int lane = threadIdx.x;

    if (w == 0 && lane == 0) g_ctr = GRIDB * 8;   // first units taken statically

    float sr0 = (lane == w) ? 1.f : 0.f,      si0 = 0.f;
    float sr1 = (lane + 32 == w) ? 1.f : 0.f, si1 = 0.f;

    for (int l = 0; l < NL; l++) {
        for (int q = 0; q < NQ; q++) {
            const float* g = weights + (l * NQ + q) * 3;
            float phi = g[0], th = g[1], om = g[2];
            float st, ct; sincosf(0.5f * th, &st, &ct);
            float sa, ca; sincosf(0.5f * (phi + om), &sa, &ca);
            float sb, cb; sincosf(0.5f * (phi - om), &sb, &cb);
            float m00r =  ca * ct, m00i = -sa * ct;
            float m01r = -cb * st, m01i = -sb * st;
            float m10r =  cb * st, m10i = -sb * st;
            float m11r =  ca * ct, m11i =  sa * ct;
            int b = 5 - q;
            if (b == 5) {
                float nr0 = m00r*sr0 - m00i*si0 + m01r*sr1 - m01i*si1;
                float ni0 = m00r*si0 + m00i*sr0 + m01r*si1 + m01i*sr1;
                float nr1 = m10r*sr0 - m10i*si0 + m11r*sr1 - m11i*si1;
                float ni1 = m10r*si0 + m10i*sr0 + m11r*si1 + m11i*sr1;
                sr0 = nr0; si0 = ni0; sr1 = nr1; si1 = ni1;
            } else {
                int msk = 1 << b;
                int bit = (lane >> b) & 1;
                float dr = bit ? m11r : m00r, di = bit ? m11i : m00i;
                float orr = bit ? m10r : m01r, oi = bit ? m10i : m01i;
                float pr, pi, nr, ni;
                pr = __shfl_xor_sync(0xffffffffu, sr0, msk);
                pi = __shfl_xor_sync(0xffffffffu, si0, msk);
                nr = dr*sr0 - di*si0 + orr*pr - oi*pi;
                ni = dr*si0 + di*sr0 + orr*pi + oi*pr;
                sr0 = nr; si0 = ni;
                pr = __shfl_xor_sync(0xffffffffu, sr1, msk);
                pi = __shfl_xor_sync(0xffffffffu, si1, msk);
                nr = dr*sr1 - di*si1 + orr*pr - oi*pi;
                ni = dr*si1 + di*sr1 + orr*pi + oi*pr;
                sr1 = nr; si1 = ni;
            }
        }
        int r = (l % (NQ - 1)) + 1;
        for (int q = 0; q < NQ; q++) {
            int t = (q + r) % NQ;
            int bc = 5 - q, bt = 5 - t;
            if (bc == 5) {
                int m = 1 << bt;
                sr1 = __shfl_xor_sync(0xffffffffu, sr1, m);
                si1 = __shfl_xor_sync(0xffffffffu, si1, m);
            } else if (bt == 5) {
                if ((lane >> bc) & 1) {
                    float tmp;
                    tmp = sr0; sr0 = sr1; sr1 = tmp;
                    tmp = si0; si0 = si1; si1 = tmp;
                }
            } else {
                int m = 1 << bt;
                int ctrl = (lane >> bc) & 1;
                float pr, pi;
                pr = __shfl_xor_sync(0xffffffffu, sr0, m);
                pi = __shfl_xor_sync(0xffffffffu, si0, m);
                if (ctrl) { sr0 = pr; si0 = pi; }
                pr = __shfl_xor_sync(0xffffffffu, sr1, m);
                pi = __shfl_xor_sync(0xffffffffu, si1, m);
                if (ctrl) { sr1 = pr; si1 = pi; }
            }
        }
    }

    g_Wh[(2 * lane)            * 64 + w] = __float2half(sr0);
    g_Wh[(2 * lane + 1)        * 64 + w] = __float2half(si0);
    g_Wh[(2 * (lane + 32))     * 64 + w] = __float2half(sr1);
    g_Wh[(2 * (lane + 32) + 1) * 64 + w] = __float2half(si1);

    if (w == 0) {
        for (int s = 0; s < 2; s++) {
            int d = lane + 32 * s;
            float m[4];
            for (int c = 0; c < 4; c++) {
                float acc = 0.f;
                for (int i = 0; i < NQ; i++) {
                    int bit = (d >> (5 - i)) & 1;
                    acc += fc_w[c * NQ + i] * (bit ? -1.f : 1.f);
                }
                m[c] = acc;
            }
            g_Mt[d] = make_float4(m[0], m[1], m[2], m[3]);
        }
        if (lane == 0)
            g_fcb = make_float4(fc_b[0], fc_b[1], fc_b[2], fc_b[3]);
    }
}

// ============================================================================
// Kernel B: persistent, 256 thr = 8 fully independent warps.
// Work unit (per warp, dynamic via atomic counter): 16 rows from each of TWO
// tiles (rows 256d+16s..+15 and +128), full N=128 processed as two sequential
// N=64 halves so accumulators stay at 64 regs while each B fragment feeds
// 4 MMAs (2 tiles x 2 n8) -> LDSM per tile halved vs single-tile.
// A: k-permuted LDG.128 straight into mma fragments (slots {2q,2q+1,2q+8,2q+9}
// <-> cols {4q..4q+3}); B smem staged in the matching permuted layout.
// No CTA-level synchronization inside the work loop.
// ============================================================================
#define STRIDE_B 144                          // 128B data + 16B pad, conflict-free
#define OF_MT   0                             // 64 float4 = 1 KB
#define OF_B    1024
#define SMEM_BYTES (OF_B + 128 * STRIDE_B)    // 1024 + 18432 = 19456

__global__ void __launch_bounds__(256, 2)
qnn_main(const float4* __restrict__ X, float4* __restrict__ out, int ntiles) {
    extern __shared__ char smc[];
    const uint32_t sm = smem_u32(smc);
    const int tid = threadIdx.x, wid = tid >> 5, lane = tid & 31;

    // ---- one-time staging: B[wrow][kpos] = Wh[wrow][colmap(kpos)] ----
    // colmap: within each k16 chunk, slot s -> col 4*((s&7)>>1) + 2*((s>>3)&1) + (s&1)
    for (int idx = tid; idx < 128 * 64; idx += 256) {
        int wrow = idx >> 6, kpos = idx & 63;
        int col = (kpos & ~15) + 4 * ((kpos & 7) >> 1) + 2 * ((kpos >> 3) & 1) + (kpos & 1);
        __half v = g_Wh[wrow * 64 + col];
        *reinterpret_cast<__half*>(smc + OF_B + wrow * STRIDE_B + kpos * 2) = v;
    }
    if (tid < 64) reinterpret_cast<float4*>(smc + OF_MT)[tid] = g_Mt[tid];
    const float4 fcb = g_fcb;
    __syncthreads();

    const int l4 = lane & 3;
    const int lq = lane >> 2;             // 0..7, row within 8-row group

    // ldsm x4 base: b[0]={n0-7,k0-7} b[1]={n0-7,k8-15} b[2]={n8-15,k0-7} b[3]={n8-15,k8-15}
    const uint32_t bB = sm + OF_B
        + (uint32_t)(((lane >> 4) & 1) * 8 + (lane & 7)) * STRIDE_B
        + ((lane >> 3) & 1) * 16;

    const float4* sMt = reinterpret_cast<const float4*>(smc + OF_MT);

    const int nunit = ntiles * 4;         // dual-tiles * 8 slices
    int u = blockIdx.x * 8 + wid;

    while (u < nunit) {
        // ---- fetch next unit early (latency hidden under this unit's work) ----
        int u_next;
        if (lane == 0) u_next = atomicAdd(&g_ctr, 1);
        u_next = __shfl_sync(0xffffffffu, u_next, 0);

        const int dual = u >> 3, slice = u & 7;
        const int row0 = dual * 256 + slice * 16 + lq;   // tile A row; tile B = +128

        // ---- A fragments: 16 LDG.128, converted to fp16 frags ----
        uint32_t ah[2][4][4];      // [tile][kc][frag]
        float ss[4] = {0.f, 0.f, 0.f, 0.f};   // [tile*2 + rowgroup]
        #pragma unroll
        for (int kc = 0; kc < 4; kc++) {
            #pragma unroll
            for (int T = 0; T < 2; T++) {
                const size_t rb = (size_t)(row0 + T * 128) * 16 + l4 + 4 * kc;
                float4 v0 = X[rb];
                float4 v1 = X[rb + 128];   // +8 rows * 16
                ss[T * 2]     += v0.x * v0.x + v0.y * v0.y + v0.z * v0.z + v0.w * v0.w;
                ss[T * 2 + 1] += v1.x * v1.x + v1.y * v1.y + v1.z * v1.z + v1.w * v1.w;
                __half2 h00 = __floats2half2_rn(v0.x, v0.y);
                __half2 h01 = __floats2half2_rn(v0.z, v0.w);
                __half2 h10 = __floats2half2_rn(v1.x, v1.y);
                __half2 h11 = __floats2half2_rn(v1.z, v1.w);
                ah[T][kc][0] = *reinterpret_cast<uint32_t*>(&h00);
                ah[T][kc][1] = *reinterpret_cast<uint32_t*>(&h10);
                ah[T][kc][2] = *reinterpret_cast<uint32_t*>(&h01);
                ah[T][kc][3] = *reinterpret_cast<uint32_t*>(&h11);
            }
        }

        // ---- two N=64 halves; B frag feeds 4 MMAs (2 tiles x 2 n8) ----
        float a[2][2][4];          // [tile][rowgroup][class] partial dots
        #pragma unroll
        for (int T = 0; T < 2; T++)
            #pragma unroll
            for (int g = 0; g < 2; g++)
                #pragma unroll
                for (int q = 0; q < 4; q++) a[T][g][q] = 0.f;

        #pragma unroll
        for (int half = 0; half < 2; half++) {
            float c[2][8][4];
            #pragma unroll
            for (int T = 0; T < 2; T++)
                #pragma unroll
                for (int j = 0; j < 8; j++)
                    #pragma unroll
                    for (int q = 0; q < 4; q++) c[T][j][q] = 0.f;

            #pragma unroll
            for (int kc = 0; kc < 4; kc++) {
                #pragma unroll
                for (int pr = 0; pr < 4; pr++) {
                    uint32_t b[4];
                    ldsm_x4(b, bB + (uint32_t)(half * 64 + pr * 16) * STRIDE_B + kc * 32);
                    #pragma unroll
                    for (int T = 0; T < 2; T++) {
                        mma16816(c[T][pr * 2],     ah[T][kc], b);
                        mma16816(c[T][pr * 2 + 1], ah[T][kc], b + 2);
                    }
                }
            }

            // epilogue for this half: p = re^2 + im^2 ; dot against Mt
            #pragma unroll
            for (int T = 0; T < 2; T++)
                #pragma unroll
                for (int j = 0; j < 8; j++) {
                    const int amp = (half * 8 + j) * 4 + l4;
                    float4 mt = sMt[amp];
                    float p0 = c[T][j][0] * c[T][j][0] + c[T][j][1] * c[T][j][1];
                    float p1 = c[T][j][2] * c[T][j][2] + c[T][j][3] * c[T][j][3];
                    a[T][0][0] += mt.x * p0; a[T][0][1] += mt.y * p0;
                    a[T][0][2] += mt.z * p0; a[T][0][3] += mt.w * p0;
                    a[T][1][0] += mt.x * p1; a[T][1][1] += mt.y * p1;
                    a[T][1][2] += mt.z * p1; a[T][1][3] += mt.w * p1;
                }
        }

        // ---- quad reductions ----
        #pragma unroll
        for (int g = 0; g < 4; g++) {
            ss[g] += __shfl_xor_sync(0xffffffffu, ss[g], 1);
            ss[g] += __shfl_xor_sync(0xffffffffu, ss[g], 2);
        }
        #pragma unroll
        for (int T = 0; T < 2; T++)
            #pragma unroll
            for (int g = 0; g < 2; g++)
                #pragma unroll
                for (int q = 0; q < 4; q++) {
                    a[T][g][q] += __shfl_xor_sync(0xffffffffu, a[T][g][q], 1);
                    a[T][g][q] += __shfl_xor_sync(0xffffffffu, a[T][g][q], 2);
                }

        if (l4 == 0) {
            #pragma unroll
            for (int T = 0; T < 2; T++)
                #pragma unroll
                for (int g = 0; g < 2; g++) {
                    float inv = 1.f / fmaxf(ss[T * 2 + g], 1e-24f);
                    float4 r;
                    r.x = a[T][g][0] * inv + fcb.x;
                    r.y = a[T][g][1] * inv + fcb.y;
                    r.z = a[T][g][2] * inv + fcb.z;
                    r.w = a[T][g][3] * inv + fcb.w;
                    out[row0 + T * 128 + g * 8] = r;
                }
        }

        u = u_next;
    }
}

// ============================================================================
// Launch
// ============================================================================
extern "C" void kernel_launch(void* const* d_in, const int* in_sizes, int n_in,
                              void* d_out, int out_size) {
    const float* x    = (const float*)d_in[0];
    const float* wts  = (const float*)d_in[1];
    const float* fc_w = (const float*)d_in[2];
    const float* fc_b = (const float*)d_in[3];

    int n_items = in_sizes[0] / DIM;   // 262144
    int ntiles  = n_items / TILE;      // 2048

    qnn_build<<<DIM, 32>>>(wts, fc_w, fc_b);
    qnn_main<<<GRIDB, 256, SMEM_BYTES>>>((const float4*)x, (float4*)d_out, ntiles);
}